// round 7
// baseline (speedup 1.0000x reference)
#include <cuda_runtime.h>
#include <math.h>

#define NPIX 262144      // 16*128*128
#define DIMD 64
#define KC   1024
#define NFINE 8192
#define NBLK 128
#define FPC   (NFINE / NBLK)         // 64 fine cells per block
#define XLO  (-12.0)
#define XRNG (24.0)
#define FWID (XRNG / (double)NFINE)
#define CWID (XRNG / (double)NBLK)
#define PADX (1e-4)
#define EPSM (1e-4f)
#define CCAP 64
#define FCAP 8

// ---- scratch (__device__ globals; zero-initialized at module load) ----
__device__ double d_m[KC], d_g[KC];
__device__ float  d_mf[KC], d_gf[KC];
__device__ float  d_of[KC];
__device__ float  d_Swf, d_Swbf, d_Sbf;
__device__ int    d_cand[NFINE * FCAP];
__device__ float4 d_fast[NFINE];             // (m, g, o, cnt-as-int)
__device__ double d_bsum[NBLK];
__device__ unsigned d_bar1, d_bar2, d_done;  // reset by last block each run

__device__ __forceinline__ void grid_barrier(unsigned* ctr) {
    __syncthreads();
    if (threadIdx.x == 0) {
        __threadfence();
        atomicAdd(ctr, 1);
        while (*(volatile unsigned*)ctr < NBLK) { }
        __threadfence();
    }
    __syncthreads();
}

__device__ __forceinline__ double wred(double v) {
    #pragma unroll
    for (int o = 16; o; o >>= 1) v += __shfl_down_sync(0xFFFFFFFFu, v, o);
    return v;
}

__device__ double wedge_peak(int c0, int c1, double xa, double xb) {
    double m0 = d_m[c0], g0 = d_g[c0];
    double m1 = d_m[c1], g1 = d_g[c1];
    double wa = fmin(fma(m0, xa, g0), fma(m1, xa, g1));
    double wb = fmin(fma(m0, xb, g0), fma(m1, xb, g1));
    double pk = fmax(wa, wb);
    if (m0 != m1) {
        double xc = (g1 - g0) / (m0 - m1);
        if (xc > xa && xc < xb) pk = fmax(pk, fma(m0, xc, g0));
    }
    return pk;
}

// ================= single fused kernel =================
__global__ void __launch_bounds__(256, 2) kAll(const float* __restrict__ emb,
                                               const float* __restrict__ w_in,
                                               const float* __restrict__ b_in,
                                               const float* __restrict__ w_out,
                                               const float4* __restrict__ x4,
                                               const float* __restrict__ b_out,
                                               float4* __restrict__ out4,
                                               float* __restrict__ out,
                                               int out_size) {
    __shared__ float smf[KC], sgf[KC];
    __shared__ float sva[256], svb[256];
    __shared__ int   sia[256], sib[256];
    __shared__ int   scand[CCAP];
    __shared__ int   scnt;
    __shared__ float speakc;
    __shared__ int   sfcnt[FPC];
    __shared__ double swl[8];
    __shared__ int s_last;

    int cc = blockIdx.x;
    int t  = threadIdx.x;
    int w  = t >> 5, lane = t & 31;

    // ---------- Phase 0: issue pixel loads NOW (overlap with table build) ----
    int gid0 = cc * 512 + t;
    int gid1 = gid0 + 256;
    float4 xv0 = x4[gid0];
    float4 xv1 = x4[gid1];

    // ---------- Phase 1: lines (warp per line: 8 lines per block) ----------
    {
        int k = cc * 8 + w;
        const float* e = emb + k * DIMD;
        double a = 0.0, c = 0.0, s = 0.0, o = 0.0;
        #pragma unroll
        for (int d = lane; d < DIMD; d += 32) {
            double ed = (double)e[d];
            a += (double)w_in[d]  * ed;
            c += (double)b_in[d]  * ed;
            s += ed * ed;
            o += (double)w_out[d] * ed;
        }
        #pragma unroll
        for (int off = 16; off; off >>= 1) {
            a += __shfl_down_sync(0xFFFFFFFFu, a, off);
            c += __shfl_down_sync(0xFFFFFFFFu, c, off);
            s += __shfl_down_sync(0xFFFFFFFFu, s, off);
            o += __shfl_down_sync(0xFFFFFFFFu, o, off);
        }
        if (lane == 0) {
            double m = -2.0 * a, g = s - 2.0 * c;
            d_m[k] = m;  d_g[k] = g;
            d_mf[k] = (float)m;  d_gf[k] = (float)g;
            d_of[k] = (float)o;
        }
    }
    if (cc == 0 && w == 0) {
        double sw = 0.0, swb = 0.0, sb = 0.0;
        for (int d = lane; d < DIMD; d += 32) {
            double ww = (double)w_in[d], bb = (double)b_in[d];
            sw += ww * ww;  swb += ww * bb;  sb += bb * bb;
        }
        #pragma unroll
        for (int off = 16; off; off >>= 1) {
            sw  += __shfl_down_sync(0xFFFFFFFFu, sw,  off);
            swb += __shfl_down_sync(0xFFFFFFFFu, swb, off);
            sb  += __shfl_down_sync(0xFFFFFFFFu, sb,  off);
        }
        if (lane == 0) { d_Swf = (float)sw;  d_Swbf = (float)swb;  d_Sbf = (float)sb; }
    }

    grid_barrier(&d_bar1);

    // ---------- Phase 2: cell build ----------
    for (int j = t; j < KC; j += 256) { smf[j] = d_mf[j]; sgf[j] = d_gf[j]; }
    __syncthreads();

    double dxa = XLO + (double)cc * CWID - PADX;
    double dxb = XLO + (double)(cc + 1) * CWID + PADX;
    float xa = (float)dxa, xb = (float)dxb;

    float ba = INFINITY, bb = INFINITY;
    int ia = 0, ib = 0;
    #pragma unroll
    for (int j = t; j < KC; j += 256) {
        float m = smf[j], g = sgf[j];
        float va = fmaf(m, xa, g);
        float vb = fmaf(m, xb, g);
        if (va < ba) { ba = va; ia = j; }
        if (vb < bb) { bb = vb; ib = j; }
    }
    // warp reduce argmin (both endpoints)
    #pragma unroll
    for (int o = 16; o; o >>= 1) {
        float ova = __shfl_down_sync(0xFFFFFFFFu, ba, o);
        int   oia = __shfl_down_sync(0xFFFFFFFFu, ia, o);
        float ovb = __shfl_down_sync(0xFFFFFFFFu, bb, o);
        int   oib = __shfl_down_sync(0xFFFFFFFFu, ib, o);
        if (ova < ba) { ba = ova; ia = oia; }
        if (ovb < bb) { bb = ovb; ib = oib; }
    }
    if (lane == 0) { sva[w] = ba; sia[w] = ia; svb[w] = bb; sib[w] = ib; }
    __syncthreads();
    if (t < 8) {
        ba = sva[t]; ia = sia[t]; bb = svb[t]; ib = sib[t];
        #pragma unroll
        for (int o = 4; o; o >>= 1) {
            float ova = __shfl_down_sync(0xFFu, ba, o, 8);
            int   oia = __shfl_down_sync(0xFFu, ia, o, 8);
            float ovb = __shfl_down_sync(0xFFu, bb, o, 8);
            int   oib = __shfl_down_sync(0xFFu, ib, o, 8);
            if (ova < ba) { ba = ova; ia = oia; }
            if (ovb < bb) { bb = ovb; ib = oib; }
        }
        if (t == 0) {
            speakc = (float)wedge_peak(ia, ib, dxa, dxb) + EPSM;
            scnt = 0;
        }
    }
    __syncthreads();

    float pkc = speakc;
    #pragma unroll
    for (int j = t; j < KC; j += 256) {
        float m = smf[j], g = sgf[j];
        float vm = fminf(fmaf(m, xa, g), fmaf(m, xb, g));
        if (vm <= pkc) {
            int slot = atomicAdd(&scnt, 1);
            if (slot < CCAP) scand[slot] = j;
        }
    }
    __syncthreads();
    int ccnt = scnt;
    if (ccnt > CCAP) {
        if (t < FPC) {
            float4 fv; fv.x = 0.f; fv.y = 0.f; fv.z = 0.f;
            fv.w = __int_as_float(9999);
            d_fast[cc * FPC + t] = fv;
        }
    } else {
        if (t < FPC) sfcnt[t] = 0;
        __syncthreads();

        int j = t >> 2;           // fine cell 0..63
        int r = t & 3;            // 4 threads per fine cell
        int fcell = cc * FPC + j;
        double fxa = XLO + (double)fcell * FWID - PADX;
        double fxb = XLO + (double)(fcell + 1) * FWID + PADX;
        float fa = (float)fxa, fb = (float)fxb;

        float fba = INFINITY, fbb = INFINITY;
        int fia = 0, fib = 0;
        for (int i = r; i < ccnt; i += 4) {
            int k = scand[i];
            float m = smf[k], g = sgf[k];
            float va = fmaf(m, fa, g);
            float vb = fmaf(m, fb, g);
            if (va < fba) { fba = va; fia = k; }
            if (vb < fbb) { fbb = vb; fib = k; }
        }
        #pragma unroll
        for (int s = 2; s > 0; s >>= 1) {
            float ova = __shfl_down_sync(0xFFFFFFFFu, fba, s, 4);
            int   oia = __shfl_down_sync(0xFFFFFFFFu, fia, s, 4);
            float ovb = __shfl_down_sync(0xFFFFFFFFu, fbb, s, 4);
            int   oib = __shfl_down_sync(0xFFFFFFFFu, fib, s, 4);
            if (ova < fba) { fba = ova; fia = oia; }
            if (ovb < fbb) { fbb = ovb; fib = oib; }
        }
        float pkf;
        if (r == 0) pkf = (float)wedge_peak(fia, fib, fxa, fxb) + EPSM;
        pkf = __shfl_sync(0xFFFFFFFFu, pkf, lane & ~3, 32);

        for (int i = r; i < ccnt; i += 4) {
            int k = scand[i];
            float m = smf[k], g = sgf[k];
            float vm = fminf(fmaf(m, fa, g), fmaf(m, fb, g));
            if (vm <= pkf) {
                int slot = atomicAdd(&sfcnt[j], 1);
                if (slot < FCAP) d_cand[fcell * FCAP + slot] = k;
            }
        }
        __syncthreads();

        if (t < FPC) {
            int fc = cc * FPC + t;
            int cnt = sfcnt[t];
            float4 fv;
            if (cnt == 1) {
                int k = d_cand[fc * FCAP];
                fv.x = smf[k]; fv.y = sgf[k]; fv.z = d_of[k];
            } else { fv.x = 0.f; fv.y = 0.f; fv.z = 0.f; }
            fv.w = __int_as_float(cnt);
            d_fast[fc] = fv;
        }
    }

    grid_barrier(&d_bar2);

    // ---------- Phase 3: 8 pixels/thread, batched independent gathers ----------
    float bo = b_out[0];
    float Sw = d_Swf, Swb = d_Swbf, Sb = d_Sbf;
    double lsum = 0.0;

    float xs[8] = { xv0.x, xv0.y, xv0.z, xv0.w, xv1.x, xv1.y, xv1.z, xv1.w };

    int cells[8];
    #pragma unroll
    for (int l = 0; l < 8; ++l) {
        float rel = (xs[l] - (float)XLO) * (float)(1.0 / FWID);
        int c = (int)floorf(rel);
        cells[l] = ((unsigned)c < (unsigned)NFINE) ? c : -1;
    }
    float4 fv[8];
    #pragma unroll
    for (int l = 0; l < 8; ++l) {
        int c = (cells[l] >= 0) ? cells[l] : 0;
        fv[l] = d_fast[c];                  // 8 independent LDG.128
    }

    float res[8];
    #pragma unroll
    for (int l = 0; l < 8; ++l) {
        float x = xs[l];
        float bestf, oval;
        int cnt = (cells[l] >= 0) ? __float_as_int(fv[l].w) : 9999;
        if (cnt == 1) {
            bestf = fmaf(fv[l].x, x, fv[l].y);
            oval  = fv[l].z;
        } else if (cnt >= 2 && cnt <= FCAP) {
            double xd = (double)x;
            double best = 1e300;
            int bk = KC;
            int base = cells[l] * FCAP;
            for (int i = 0; i < cnt; ++i) {
                int k = d_cand[base + i];
                double v = fma(d_m[k], xd, d_g[k]);
                if (v < best || (v == best && k < bk)) { best = v; bk = k; }
            }
            bestf = (float)best;
            oval  = d_of[bk];
        } else {
            double xd = (double)x;
            double best = 1e300;
            int bk = KC;
            for (int k = 0; k < KC; ++k) {
                double v = fma(d_m[k], xd, d_g[k]);
                if (v < best) { best = v; bk = k; }
            }
            bestf = (float)best;
            oval  = d_of[bk];
        }
        res[l] = oval + bo;
        lsum += (double)(bestf + fmaf(x, fmaf(x, Sw, 2.0f * Swb), Sb));
    }
    float4 ov0, ov1;
    ov0.x = res[0]; ov0.y = res[1]; ov0.z = res[2]; ov0.w = res[3];
    ov1.x = res[4]; ov1.y = res[5]; ov1.z = res[6]; ov1.w = res[7];
    out4[gid0] = ov0;
    out4[gid1] = ov1;

    // ---------- Phase 4: loss reduction (shuffle-based, fixed order) ----------
    double v = wred(lsum);
    if (lane == 0) swl[w] = v;
    __syncthreads();
    if (t < 8) {
        double v2 = swl[t];
        #pragma unroll
        for (int o = 4; o; o >>= 1) v2 += __shfl_down_sync(0xFFu, v2, o, 8);
        if (t == 0) {
            d_bsum[cc] = v2;
            __threadfence();
            unsigned dn = atomicAdd(&d_done, 1);
            s_last = (dn == NBLK - 1);
        }
    }
    __syncthreads();

    if (s_last) {
        __threadfence();
        double lv = (t < NBLK) ? d_bsum[t] : 0.0;
        lv = wred(lv);
        if (lane == 0) swl[w] = lv;
        __syncthreads();
        if (t == 0) {
            double tot = ((swl[0] + swl[1]) + (swl[2] + swl[3]))
                       + ((swl[4] + swl[5]) + (swl[6] + swl[7]));
            if (out_size > NPIX)
                out[NPIX] = (float)(12.5 * tot / ((double)NPIX * (double)DIMD));
            // reset barrier state for the next graph replay (stream-ordered)
            d_bar1 = 0; d_bar2 = 0; d_done = 0;
            __threadfence();
        }
    }
}

extern "C" void kernel_launch(void* const* d_in, const int* in_sizes, int n_in,
                              void* d_out, int out_size) {
    const float* x     = (const float*)d_in[0];
    const float* w_in  = (const float*)d_in[1];
    const float* b_in  = (const float*)d_in[2];
    const float* emb   = (const float*)d_in[3];
    const float* w_out = (const float*)d_in[4];
    const float* b_out = (const float*)d_in[5];
    float* out = (float*)d_out;

    kAll<<<NBLK, 256>>>(emb, w_in, b_in, w_out,
                        (const float4*)x, b_out,
                        (float4*)out, out, out_size);
}

// round 8
// speedup vs baseline: 37.5938x; 37.5938x over previous
#include <cuda_runtime.h>
#include <math.h>

#define NPIX 262144      // 16*128*128
#define DIMD 64
#define KC   1024
#define NFINE 8192
#define NCOARSE 256
#define FPC   (NFINE / NCOARSE)      // 32 fine cells per coarse cell
#define XLO  (-12.0)
#define XRNG (24.0)
#define FWID (XRNG / (double)NFINE)
#define CWID (XRNG / (double)NCOARSE)
#define PADX (1e-4)
#define EPSM (1e-4f)
#define CCAP 64
#define FCAP 8
#define NBLKB 128                    // kB: 128 blocks * 256 threads * 8 px = NPIX

// ---- scratch (__device__ globals; zero-initialized at module load) ----
__device__ double d_m[KC], d_g[KC];
__device__ float  d_mf[KC], d_gf[KC];
__device__ float  d_of[KC];
__device__ float  d_Swf, d_Swbf, d_Sbf;
__device__ int    d_cand[NFINE * FCAP];
__device__ float4 d_fast[NFINE];             // (m, g, o, cnt-as-int)
__device__ double d_bsum[NBLKB];
__device__ volatile unsigned d_barA;         // kA grid barrier (reset by kB)
__device__ unsigned d_doneB;                 // kB last-block counter (reset by kA)

__device__ double wedge_peak(int c0, int c1, double xa, double xb) {
    double m0 = d_m[c0], g0 = d_g[c0];
    double m1 = d_m[c1], g1 = d_g[c1];
    double wa = fmin(fma(m0, xa, g0), fma(m1, xa, g1));
    double wb = fmin(fma(m0, xb, g0), fma(m1, xb, g1));
    double pk = fmax(wa, wb);
    if (m0 != m1) {
        double xc = (g1 - g0) / (m0 - m1);
        if (xc > xa && xc < xb) pk = fmax(pk, fma(m0, xc, g0));
    }
    return pk;
}

// ================= kA: lines + grid barrier + cell build (R4-proven) =================
__global__ void __launch_bounds__(256) kA(const float* __restrict__ emb,
                                          const float* __restrict__ w_in,
                                          const float* __restrict__ b_in,
                                          const float* __restrict__ w_out) {
    __shared__ float smf[KC], sgf[KC];
    __shared__ float sva[256], svb[256];
    __shared__ int   sia[256], sib[256];
    __shared__ int   scand[CCAP];
    __shared__ int   scnt;
    __shared__ float speakc;
    __shared__ int   sfcnt[FPC];

    int cc = blockIdx.x;
    int t  = threadIdx.x;
    int w  = t >> 5, lane = t & 31;

    if (cc == 0 && t == 0) d_doneB = 0;   // arm kB's last-block counter

    // --- Phase 1: this block computes lines cc*4 .. cc*4+3 (warp per line) ---
    if (w < 4) {
        int k = cc * 4 + w;
        const float* e = emb + k * DIMD;
        double a = 0.0, c = 0.0, s = 0.0, o = 0.0;
        #pragma unroll
        for (int d = lane; d < DIMD; d += 32) {
            double ed = (double)e[d];
            a += (double)w_in[d]  * ed;
            c += (double)b_in[d]  * ed;
            s += ed * ed;
            o += (double)w_out[d] * ed;
        }
        #pragma unroll
        for (int off = 16; off; off >>= 1) {
            a += __shfl_down_sync(0xFFFFFFFFu, a, off);
            c += __shfl_down_sync(0xFFFFFFFFu, c, off);
            s += __shfl_down_sync(0xFFFFFFFFu, s, off);
            o += __shfl_down_sync(0xFFFFFFFFu, o, off);
        }
        if (lane == 0) {
            double m = -2.0 * a, g = s - 2.0 * c;
            d_m[k] = m;  d_g[k] = g;
            d_mf[k] = (float)m;  d_gf[k] = (float)g;
            d_of[k] = (float)o;
        }
    } else if (cc == 0 && w == 4) {
        double sw = 0.0, swb = 0.0, sb = 0.0;
        for (int d = lane; d < DIMD; d += 32) {
            double ww = (double)w_in[d], bb = (double)b_in[d];
            sw += ww * ww;  swb += ww * bb;  sb += bb * bb;
        }
        #pragma unroll
        for (int off = 16; off; off >>= 1) {
            sw  += __shfl_down_sync(0xFFFFFFFFu, sw,  off);
            swb += __shfl_down_sync(0xFFFFFFFFu, swb, off);
            sb  += __shfl_down_sync(0xFFFFFFFFu, sb,  off);
        }
        if (lane == 0) { d_Swf = (float)sw;  d_Swbf = (float)swb;  d_Sbf = (float)sb; }
    }
    __syncthreads();

    // --- software grid barrier (256 blocks co-resident) ---
    if (t == 0) {
        __threadfence();
        atomicAdd((unsigned*)&d_barA, 1);
        while (d_barA < NCOARSE) { }
        __threadfence();
    }
    __syncthreads();

    // --- load all lines into smem ---
    for (int j = t; j < KC; j += 256) { smf[j] = d_mf[j]; sgf[j] = d_gf[j]; }
    __syncthreads();

    // --- Phase A: coarse cell endpoint argmin ---
    double dxa = XLO + (double)cc * CWID - PADX;
    double dxb = XLO + (double)(cc + 1) * CWID + PADX;
    float xa = (float)dxa, xb = (float)dxb;

    float ba = INFINITY, bb = INFINITY;
    int ia = 0, ib = 0;
    #pragma unroll
    for (int j = t; j < KC; j += 256) {
        float m = smf[j], g = sgf[j];
        float va = fmaf(m, xa, g);
        float vb = fmaf(m, xb, g);
        if (va < ba) { ba = va; ia = j; }
        if (vb < bb) { bb = vb; ib = j; }
    }
    sva[t] = ba; sia[t] = ia; svb[t] = bb; sib[t] = ib;
    __syncthreads();
    for (int s = 128; s > 0; s >>= 1) {
        if (t < s) {
            if (sva[t + s] < sva[t]) { sva[t] = sva[t + s]; sia[t] = sia[t + s]; }
            if (svb[t + s] < svb[t]) { svb[t] = svb[t + s]; sib[t] = sib[t + s]; }
        }
        __syncthreads();
    }
    if (t == 0) {
        speakc = (float)wedge_peak(sia[0], sib[0], dxa, dxb) + EPSM;
        scnt = 0;
    }
    __syncthreads();

    // --- Phase A2: collect coarse candidates ---
    float pkc = speakc;
    #pragma unroll
    for (int j = t; j < KC; j += 256) {
        float m = smf[j], g = sgf[j];
        float vm = fminf(fmaf(m, xa, g), fmaf(m, xb, g));
        if (vm <= pkc) {
            int slot = atomicAdd(&scnt, 1);
            if (slot < CCAP) scand[slot] = j;
        }
    }
    __syncthreads();
    int ccnt = scnt;
    if (ccnt > CCAP) {
        if (t < FPC) {
            float4 fv; fv.x = 0.f; fv.y = 0.f; fv.z = 0.f;
            fv.w = __int_as_float(9999);
            d_fast[cc * FPC + t] = fv;
        }
        return;
    }
    if (t < FPC) sfcnt[t] = 0;
    __syncthreads();

    // --- Phase B: fine cells. 8 threads (r) per fine cell (j). ---
    int j = t >> 3;
    int r = t & 7;
    int fcell = cc * FPC + j;
    double fxa = XLO + (double)fcell * FWID - PADX;
    double fxb = XLO + (double)(fcell + 1) * FWID + PADX;
    float fa = (float)fxa, fb = (float)fxb;

    float fba = INFINITY, fbb = INFINITY;
    int fia = 0, fib = 0;
    for (int i = r; i < ccnt; i += 8) {
        int k = scand[i];
        float m = smf[k], g = sgf[k];
        float va = fmaf(m, fa, g);
        float vb = fmaf(m, fb, g);
        if (va < fba) { fba = va; fia = k; }
        if (vb < fbb) { fbb = vb; fib = k; }
    }
    #pragma unroll
    for (int s = 4; s > 0; s >>= 1) {
        float ova = __shfl_down_sync(0xFFFFFFFFu, fba, s, 8);
        int   oia = __shfl_down_sync(0xFFFFFFFFu, fia, s, 8);
        float ovb = __shfl_down_sync(0xFFFFFFFFu, fbb, s, 8);
        int   oib = __shfl_down_sync(0xFFFFFFFFu, fib, s, 8);
        if (ova < fba) { fba = ova; fia = oia; }
        if (ovb < fbb) { fbb = ovb; fib = oib; }
    }
    float pkf;
    if (r == 0) pkf = (float)wedge_peak(fia, fib, fxa, fxb) + EPSM;
    pkf = __shfl_sync(0xFFFFFFFFu, pkf, (t & ~7) & 31, 32);

    for (int i = r; i < ccnt; i += 8) {
        int k = scand[i];
        float m = smf[k], g = sgf[k];
        float vm = fminf(fmaf(m, fa, g), fmaf(m, fb, g));
        if (vm <= pkf) {
            int slot = atomicAdd(&sfcnt[j], 1);
            if (slot < FCAP) d_cand[fcell * FCAP + slot] = k;
        }
    }
    __syncthreads();

    if (t < FPC) {
        int fc = cc * FPC + t;
        int cnt = sfcnt[t];
        float4 fv;
        if (cnt == 1) {
            int k = d_cand[fc * FCAP];
            fv.x = smf[k]; fv.y = sgf[k]; fv.z = d_of[k];
        } else { fv.x = 0.f; fv.y = 0.f; fv.z = 0.f; }
        fv.w = __int_as_float(cnt);
        d_fast[fc] = fv;
    }
}

// ================= kB: 8 px/thread, batched gathers, fused finalize =================
__global__ void __launch_bounds__(256) kB(const float4* __restrict__ x4,
                                          const float* __restrict__ b_out,
                                          float4* __restrict__ out4,
                                          float* __restrict__ out,
                                          int out_size) {
    __shared__ double swl[8];
    __shared__ int s_last;
    if (blockIdx.x == 0 && threadIdx.x == 0) d_barA = 0;   // re-arm kA's barrier

    int t = threadIdx.x;
    int w = t >> 5, lane = t & 31;
    int gid0 = blockIdx.x * 512 + t;       // two coalesced float4 tiles per block
    int gid1 = gid0 + 256;

    float4 xv0 = x4[gid0];                 // issued immediately (MLP)
    float4 xv1 = x4[gid1];
    float bo = b_out[0];
    float Sw = d_Swf, Swb = d_Swbf, Sb = d_Sbf;

    float xs[8] = { xv0.x, xv0.y, xv0.z, xv0.w, xv1.x, xv1.y, xv1.z, xv1.w };

    int cells[8];
    #pragma unroll
    for (int l = 0; l < 8; ++l) {
        float rel = (xs[l] - (float)XLO) * (float)(1.0 / FWID);
        int c = (int)floorf(rel);
        cells[l] = ((unsigned)c < (unsigned)NFINE) ? c : -1;
    }
    float4 fv[8];
    #pragma unroll
    for (int l = 0; l < 8; ++l) {
        int c = (cells[l] >= 0) ? cells[l] : 0;
        fv[l] = d_fast[c];                  // 8 independent LDG.128
    }

    double lsum = 0.0;
    float res[8];
    #pragma unroll
    for (int l = 0; l < 8; ++l) {
        float x = xs[l];
        float bestf, oval;
        int cnt = (cells[l] >= 0) ? __float_as_int(fv[l].w) : 9999;
        if (cnt == 1) {
            bestf = fmaf(fv[l].x, x, fv[l].y);
            oval  = fv[l].z;
        } else if (cnt >= 2 && cnt <= FCAP) {
            double xd = (double)x;
            double best = 1e300;
            int bk = KC;
            int base = cells[l] * FCAP;
            for (int i = 0; i < cnt; ++i) {
                int k = d_cand[base + i];
                double v = fma(d_m[k], xd, d_g[k]);
                if (v < best || (v == best && k < bk)) { best = v; bk = k; }
            }
            bestf = (float)best;
            oval  = d_of[bk];
        } else {
            double xd = (double)x;
            double best = 1e300;
            int bk = KC;
            for (int k = 0; k < KC; ++k) {
                double v = fma(d_m[k], xd, d_g[k]);
                if (v < best) { best = v; bk = k; }
            }
            bestf = (float)best;
            oval  = d_of[bk];
        }
        res[l] = oval + bo;
        lsum += (double)(bestf + fmaf(x, fmaf(x, Sw, 2.0f * Swb), Sb));
    }
    float4 ov0, ov1;
    ov0.x = res[0]; ov0.y = res[1]; ov0.z = res[2]; ov0.w = res[3];
    ov1.x = res[4]; ov1.y = res[5]; ov1.z = res[6]; ov1.w = res[7];
    out4[gid0] = ov0;
    out4[gid1] = ov1;

    // ---- per-block loss reduction (shuffle, fixed order) ----
    #pragma unroll
    for (int o = 16; o; o >>= 1) lsum += __shfl_down_sync(0xFFFFFFFFu, lsum, o);
    if (lane == 0) swl[w] = lsum;
    __syncthreads();
    if (t == 0) {
        double v2 = ((swl[0] + swl[1]) + (swl[2] + swl[3]))
                  + ((swl[4] + swl[5]) + (swl[6] + swl[7]));
        d_bsum[blockIdx.x] = v2;
        __threadfence();
        unsigned dn = atomicAdd(&d_doneB, 1);
        s_last = (dn == NBLKB - 1);
    }
    __syncthreads();

    if (s_last) {
        // last block: deterministic fixed-order reduction of 128 partials
        __threadfence();
        double lv = (t < NBLKB) ? d_bsum[t] : 0.0;
        #pragma unroll
        for (int o = 16; o; o >>= 1) lv += __shfl_down_sync(0xFFFFFFFFu, lv, o);
        if (lane == 0) swl[w] = lv;
        __syncthreads();
        if (t == 0) {
            double tot = ((swl[0] + swl[1]) + (swl[2] + swl[3]));  // warps 4-7 held zeros
            tot += ((swl[4] + swl[5]) + (swl[6] + swl[7]));
            if (out_size > NPIX)
                out[NPIX] = (float)(12.5 * tot / ((double)NPIX * (double)DIMD));
        }
    }
}

extern "C" void kernel_launch(void* const* d_in, const int* in_sizes, int n_in,
                              void* d_out, int out_size) {
    const float* x     = (const float*)d_in[0];
    const float* w_in  = (const float*)d_in[1];
    const float* b_in  = (const float*)d_in[2];
    const float* emb   = (const float*)d_in[3];
    const float* w_out = (const float*)d_in[4];
    const float* b_out = (const float*)d_in[5];
    float* out = (float*)d_out;

    kA<<<NCOARSE, 256>>>(emb, w_in, b_in, w_out);
    kB<<<NBLKB, 256>>>((const float4*)x, b_out, (float4*)out, out, out_size);
}